// round 13
// baseline (speedup 1.0000x reference)
#include <cuda_runtime.h>
#include <cuda_fp16.h>
#include <math.h>
#include <stdint.h>

#define BB 2
#define SS 2048
#define DD 1024
#define HH 16
#define HDIM 64
#define MM (BB*SS)

typedef __half f16;

// ---------------------------------------------------------------------------
// Scratch (__device__ globals; no runtime allocation)
// ---------------------------------------------------------------------------
__device__ f16 g_x16[MM*DD];
__device__ f16 g_wq16[DD*DD], g_wk16[DD*DD], g_wv16[DD*DD], g_wo16[DD*DD];
__device__ f16 g_q16[MM*DD], g_k16[MM*DD], g_v16[MM*DD], g_a16[MM*DD];
#define NMW (BB * SS * (SS / 32))
__device__ uint32_t g_pm[NMW];

// ---------------------------------------------------------------------------
// Helpers
// ---------------------------------------------------------------------------
__device__ __forceinline__ uint32_t pack_f16(f16 a, f16 b) {
    __half2 t = __halves2half2(a, b);
    return *reinterpret_cast<uint32_t*>(&t);
}

__device__ __forceinline__ void mma_f16(float* c, const uint32_t* a, const uint32_t* b) {
    asm volatile(
        "mma.sync.aligned.m16n8k16.row.col.f32.f16.f16.f32 "
        "{%0,%1,%2,%3}, {%4,%5,%6,%7}, {%8,%9}, {%0,%1,%2,%3};\n"
        : "+f"(c[0]), "+f"(c[1]), "+f"(c[2]), "+f"(c[3])
        : "r"(a[0]), "r"(a[1]), "r"(a[2]), "r"(a[3]), "r"(b[0]), "r"(b[1]));
}

__device__ __forceinline__ uint32_t smem_u32(const void* p) {
    return (uint32_t)__cvta_generic_to_shared(p);
}

#define CP16(sa, gp) \
    asm volatile("cp.async.cg.shared.global [%0], [%1], 16;\n" :: "r"(sa), "l"(gp))
#define CP_COMMIT() asm volatile("cp.async.commit_group;\n" ::: "memory")
template<int N>
__device__ __forceinline__ void cp_wait() {
    asm volatile("cp.async.wait_group %0;\n" :: "n"(N) : "memory");
}

#define LDMX2T(r0, r1, addr) \
    asm volatile("ldmatrix.sync.aligned.m8n8.x2.trans.shared.b16 {%0,%1}, [%2];\n" \
                 : "=r"(r0), "=r"(r1) : "r"(addr))
#define LDMX4(r0, r1, r2, r3, addr) \
    asm volatile("ldmatrix.sync.aligned.m8n8.x4.shared.b16 {%0,%1,%2,%3}, [%4];\n" \
                 : "=r"(r0), "=r"(r1), "=r"(r2), "=r"(r3) : "r"(addr))

// softmax in exp2 domain: 0.125 * log2(e), folded into q at qkv epilogue
#define SCL2 0.18033688011112042f

// ---------------------------------------------------------------------------
// Convert kernel: x, Wq, Wk, Wv, Wo -> single fp16
// ---------------------------------------------------------------------------
#define NX4 (MM * DD / 4)
#define NW4 (DD * DD / 4)
#define NSPLIT (NX4 + 4 * NW4)

__global__ void split_all(const float* __restrict__ x,
                          const float* __restrict__ wq, const float* __restrict__ wk,
                          const float* __restrict__ wv, const float* __restrict__ wo,
                          f16* __restrict__ x16,
                          f16* __restrict__ wq16, f16* __restrict__ wk16,
                          f16* __restrict__ wv16, f16* __restrict__ wo16) {
    int i = blockIdx.x * blockDim.x + threadIdx.x;
    if (i >= NSPLIT) return;
    const float* s; f16* d; int off;
    if (i < NX4)                { s = x;  d = x16;  off = i; }
    else if (i < NX4 + NW4)     { s = wq; d = wq16; off = i - NX4; }
    else if (i < NX4 + 2 * NW4) { s = wk; d = wk16; off = i - NX4 - NW4; }
    else if (i < NX4 + 3 * NW4) { s = wv; d = wv16; off = i - NX4 - 2 * NW4; }
    else                        { s = wo; d = wo16; off = i - NX4 - 3 * NW4; }
    float4 v = ((const float4*)s)[off];
    uint2 u;
    u.x = pack_f16(__float2half_rn(v.x), __float2half_rn(v.y));
    u.y = pack_f16(__float2half_rn(v.z), __float2half_rn(v.w));
    ((uint2*)d)[off] = u;
}

// ---------------------------------------------------------------------------
// Mask pack: int32 (0/1) -> 1 bit per element
// ---------------------------------------------------------------------------
__global__ void pack_mask(const int* __restrict__ mask, uint32_t* __restrict__ pm) {
    int w = blockIdx.x * blockDim.x + threadIdx.x;
    if (w >= NMW) return;
    const int4* src = (const int4*)(mask + (size_t)w * 32);
    uint32_t bits = 0;
    #pragma unroll
    for (int j = 0; j < 8; j++) {
        int4 m = src[j];
        bits |= (uint32_t)(m.x == 1) << (4 * j);
        bits |= (uint32_t)(m.y == 1) << (4 * j + 1);
        bits |= (uint32_t)(m.z == 1) << (4 * j + 2);
        bits |= (uint32_t)(m.w == 1) << (4 * j + 3);
    }
    pm[w] = bits;
}

// ---------------------------------------------------------------------------
// fp16 single-pass GEMM: 128x128 CTA tile, 8 warps (4M x 2N, 32x64 warp tile),
// 3-stage cp.async. (unchanged from R12)
// ---------------------------------------------------------------------------
#define GKC 32
#define GPAD 40
#define GA_ELE (128 * GPAD)
#define GB_ELE (128 * GPAD)
#define G1STG (GA_ELE + GB_ELE)
#define G1O_WH GA_ELE
#define GEMM1_SMEM (3 * G1STG * 2)

__device__ __forceinline__ void gemm1_issue(const f16* __restrict__ A,
                                            const f16* __restrict__ W,
                                            int m0, int n0, int kt,
                                            uint32_t sbase, int tid) {
    #pragma unroll
    for (int j = 0; j < 2; j++) {
        int cidx = tid + 256 * j;
        int row = cidx >> 2, col = (cidx & 3) * 8;
        uint32_t so = sbase + (row * GPAD + col) * 2;
        CP16(so, A + (size_t)(m0 + row) * DD + kt + col);
    }
    #pragma unroll
    for (int j = 0; j < 2; j++) {
        int cidx = tid + 256 * j;
        int row = cidx >> 2, col = (cidx & 3) * 8;
        uint32_t so = sbase + (G1O_WH + row * GPAD + col) * 2;
        CP16(so, W + (size_t)(n0 + row) * DD + kt + col);
    }
}

__device__ __forceinline__ void gemm1_main(const f16* __restrict__ A,
                                           const f16* __restrict__ W,
                                           int m0, int n0,
                                           float c[2][8][4]) {
    extern __shared__ f16 sm16[];
    const uint32_t sb = smem_u32(sm16);
    const int tid = threadIdx.x;
    const int wid = tid >> 5, lane = tid & 31;
    const int wm = (wid >> 1) * 32, wn = (wid & 1) * 64;
    const int a_lm = (lane & 15) * GPAD + (lane >> 4) * 8;
    const int b_lm = (wn + (lane >> 4) * 8 + (lane & 7)) * GPAD + ((lane >> 3) & 1) * 8;

    gemm1_issue(A, W, m0, n0, 0,   sb,             tid); CP_COMMIT();
    gemm1_issue(A, W, m0, n0, GKC, sb + G1STG * 2, tid); CP_COMMIT();

    const int NCH = DD / GKC;
    for (int ch = 0; ch < NCH; ch++) {
        if (ch + 2 < NCH)
            gemm1_issue(A, W, m0, n0, (ch + 2) * GKC,
                        sb + ((ch + 2) % 3) * G1STG * 2, tid);
        CP_COMMIT();
        cp_wait<2>();
        __syncthreads();

        const uint32_t sA = sb + ((ch % 3) * G1STG) * 2;

        #pragma unroll
        for (int ks = 0; ks < 2; ks++) {
            const int k0 = ks * 16;
            uint32_t ah[2][4];
            #pragma unroll
            for (int mt = 0; mt < 2; mt++) {
                uint32_t ad = sA + (uint32_t)((wm + mt * 16) * GPAD + a_lm + k0) * 2;
                LDMX4(ah[mt][0], ah[mt][1], ah[mt][2], ah[mt][3], ad);
            }
            #pragma unroll
            for (int j = 0; j < 4; j++) {
                uint32_t bd = sA + (uint32_t)(G1O_WH + 2 * j * 8 * GPAD + b_lm + k0) * 2;
                uint32_t bh[4];
                LDMX4(bh[0], bh[1], bh[2], bh[3], bd);
                #pragma unroll
                for (int sub = 0; sub < 2; sub++) {
                    const int nt = 2 * j + sub;
                    #pragma unroll
                    for (int mt = 0; mt < 2; mt++)
                        mma_f16(c[mt][nt], ah[mt], &bh[2 * sub]);
                }
            }
        }
        __syncthreads();
    }
}

__global__ void __launch_bounds__(256, 2)
qkv_gemm(const f16* __restrict__ x16,
         const f16* __restrict__ wq16, const f16* __restrict__ wk16,
         const f16* __restrict__ wv16,
         f16* __restrict__ q16, f16* __restrict__ k16, f16* __restrict__ v16) {
    const int z = blockIdx.z;
    const f16* Wh = (z == 0) ? wq16 : (z == 1) ? wk16 : wv16;
    f16* Y = (z == 0) ? q16 : (z == 1) ? k16 : v16;
    const int m0 = blockIdx.y * 128, n0 = blockIdx.x * 128;
    const int tid = threadIdx.x;
    const int wid = tid >> 5, lane = tid & 31;
    const int g = lane >> 2, t = lane & 3;
    const int wm = (wid >> 1) * 32, wn = (wid & 1) * 64;

    float c[2][8][4] = {};
    gemm1_main(x16, Wh, m0, n0, c);

    // q pre-scaled by SCL2 (softmax exp2-domain fold); k, v unscaled
    const float qs = (z == 0) ? SCL2 : 1.0f;

    #pragma unroll
    for (int mt = 0; mt < 2; mt++) {
        const int r = m0 + wm + mt * 16 + g;
        #pragma unroll
        for (int nt = 0; nt < 8; nt++) {
            const int n = n0 + wn + nt * 8 + 2 * t;
            uint32_t u0 = pack_f16(__float2half_rn(c[mt][nt][0] * qs),
                                   __float2half_rn(c[mt][nt][1] * qs));
            uint32_t u1 = pack_f16(__float2half_rn(c[mt][nt][2] * qs),
                                   __float2half_rn(c[mt][nt][3] * qs));
            *(uint32_t*)&Y[(size_t)r * DD + n] = u0;
            *(uint32_t*)&Y[(size_t)(r + 8) * DD + n] = u1;
        }
    }
}

__global__ void __launch_bounds__(256, 2)
out_gemm(const f16* __restrict__ a16, const f16* __restrict__ wo16,
         const float* __restrict__ bo, float* __restrict__ out) {
    const int m0 = blockIdx.y * 128, n0 = blockIdx.x * 128;
    const int tid = threadIdx.x;
    const int wid = tid >> 5, lane = tid & 31;
    const int g = lane >> 2, t = lane & 3;
    const int wm = (wid >> 1) * 32, wn = (wid & 1) * 64;

    float c[2][8][4] = {};
    gemm1_main(a16, wo16, m0, n0, c);

    #pragma unroll
    for (int mt = 0; mt < 2; mt++) {
        const int r = m0 + wm + mt * 16 + g;
        #pragma unroll
        for (int nt = 0; nt < 8; nt++) {
            const int n = n0 + wn + nt * 8 + 2 * t;
            float bx = bo[n], by = bo[n + 1];
            float2 o0 = { c[mt][nt][0] + bx, c[mt][nt][1] + by };
            float2 o1 = { c[mt][nt][2] + bx, c[mt][nt][3] + by };
            *(float2*)&out[(size_t)r * DD + n] = o0;
            *(float2*)&out[(size_t)(r + 8) * DD + n] = o1;
        }
    }
}

// ---------------------------------------------------------------------------
// Flash attention: 128 q-rows/CTA, 4 warps x 32 rows — every K/V fragment
// feeds 2 MMAs (LDSM per MMA halved). fp16 1-pass, no-max exp2 softmax,
// double-buffered KV, packed mask. 128 threads, 2 CTAs/SM.
// ---------------------------------------------------------------------------
#define APAD 72
#define AT_ELE (64 * APAD)
#define AO_Q 0
#define AO_K(s) ((2 + 2 * (s)) * AT_ELE)
#define AO_V(s) ((3 + 2 * (s)) * AT_ELE)
#define ATTN_SMEM (6 * AT_ELE * 2)   // Q(2 tiles) + 2x(K+V) = 55296 B

__device__ __forceinline__ void attn_issue_kv(const f16* __restrict__ K16,
                                              const f16* __restrict__ V16,
                                              size_t brow, size_t hoff, int kt,
                                              uint32_t sb, int s, int tid) {
    #pragma unroll
    for (int j = 0; j < 4; j++) {
        int cidx = tid + 128 * j;
        int row = cidx >> 3, col = (cidx & 7) * 8;
        uint32_t so = sb + (AO_K(s) + row * APAD + col) * 2;
        size_t go = (brow + kt + row) * DD + hoff + col;
        CP16(so,              K16 + go);
        CP16(so + AT_ELE * 2, V16 + go);
    }
}

__global__ void __launch_bounds__(128, 2)
attn_kernel(const f16* __restrict__ Q16,
            const f16* __restrict__ K16, const f16* __restrict__ V16,
            const uint32_t* __restrict__ pm,
            f16* __restrict__ O16)
{
    extern __shared__ f16 smA[];
    const uint32_t sb = smem_u32(smA);
    const int tid = threadIdx.x;
    const int wid = tid >> 5, lane = tid & 31;
    const int g = lane >> 2, t = lane & 3;
    const int q0 = blockIdx.x * 128;
    const int h = blockIdx.y;
    const int b = blockIdx.z;
    const int wm = wid * 32;

    const size_t hoff = (size_t)h * HDIM;
    const size_t brow = (size_t)b * SS;

    // ---- Issue Q (128 rows), KV0, KV1 ----
    #pragma unroll
    for (int j = 0; j < 8; j++) {
        int cidx = tid + 128 * j;
        int row = cidx >> 3, col = (cidx & 7) * 8;
        uint32_t so = sb + (AO_Q + row * APAD + col) * 2;
        CP16(so, Q16 + (brow + q0 + row) * DD + hoff + col);
    }
    CP_COMMIT();
    attn_issue_kv(K16, V16, brow, hoff, 0,  sb, 0, tid); CP_COMMIT();
    attn_issue_kv(K16, V16, brow, hoff, 64, sb, 1, tid); CP_COMMIT();

    cp_wait<2>();
    __syncthreads();

    // ---- Hoist Q fragments (2 row blocks x 4 k-steps) ----
    uint32_t aq[2][4][4];
    {
        const int a_lm = (lane & 15) * APAD + (lane >> 4) * 8;
        #pragma unroll
        for (int mt = 0; mt < 2; mt++)
            #pragma unroll
            for (int kk = 0; kk < 4; kk++) {
                uint32_t ad = sb + (uint32_t)(AO_Q + (wm + mt * 16) * APAD + a_lm + kk * 16) * 2;
                LDMX4(aq[mt][kk][0], aq[mt][kk][1], aq[mt][kk][2], aq[mt][kk][3], ad);
            }
    }

    float o[2][8][4] = {};
    float l0[2] = {0.f, 0.f}, l1[2] = {0.f, 0.f};
    const int NKT = SS / 64;

    const int k_lm = ((lane >> 4) * 8 + (lane & 7)) * APAD + ((lane >> 3) & 1) * 8;
    const uint32_t* pr[2][2];
    #pragma unroll
    for (int mt = 0; mt < 2; mt++) {
        const int mrow = q0 + wm + mt * 16 + g;
        pr[mt][0] = pm + (brow + mrow) * (SS / 32);
        pr[mt][1] = pr[mt][0] + 8 * (SS / 32);
    }
    const int s0 = 2 * t;

    for (int it = 0; it < NKT; it++) {
        cp_wait<1>();
        __syncthreads();

        const int buf = it & 1;
        const uint32_t kbase = sb + (uint32_t)AO_K(buf) * 2;
        const uint32_t vbase = sb + (uint32_t)(AO_V(buf) + (lane & 15) * APAD) * 2;

        // ---- S = Q @ K^T: each K fragment feeds both row blocks ----
        float cs[2][8][4] = {};
        #pragma unroll
        for (int kk = 0; kk < 4; kk++) {
            const int k0 = kk * 16;
            #pragma unroll
            for (int j = 0; j < 4; j++) {
                uint32_t kd = kbase + (uint32_t)(2 * j * 8 * APAD + k_lm + k0) * 2;
                uint32_t bh[4];
                LDMX4(bh[0], bh[1], bh[2], bh[3], kd);
                #pragma unroll
                for (int mt = 0; mt < 2; mt++) {
                    mma_f16(cs[mt][2 * j],     aq[mt][kk], &bh[0]);
                    mma_f16(cs[mt][2 * j + 1], aq[mt][kk], &bh[2]);
                }
            }
        }

        // ---- P = exp2(S) (q pre-scaled), masked -> 0; accumulate row sums ----
        #pragma unroll
        for (int mt = 0; mt < 2; mt++) {
            uint2 w0 = *(const uint2*)(pr[mt][0] + it * 2);
            uint2 w1 = *(const uint2*)(pr[mt][1] + it * 2);
            #pragma unroll
            for (int nt = 0; nt < 8; nt++) {
                const uint32_t wa = (nt < 4) ? w0.x : w0.y;
                const uint32_t wb = (nt < 4) ? w1.x : w1.y;
                const int p = 8 * (nt & 3) + s0;
                float e0 = exp2f(cs[mt][nt][0]);
                float e1 = exp2f(cs[mt][nt][1]);
                float e2 = exp2f(cs[mt][nt][2]);
                float e3 = exp2f(cs[mt][nt][3]);
                cs[mt][nt][0] = ((wa >> p) & 1)       ? 0.f : e0;
                cs[mt][nt][1] = ((wa >> (p + 1)) & 1) ? 0.f : e1;
                cs[mt][nt][2] = ((wb >> p) & 1)       ? 0.f : e2;
                cs[mt][nt][3] = ((wb >> (p + 1)) & 1) ? 0.f : e3;
                l0[mt] += cs[mt][nt][0] + cs[mt][nt][1];
                l1[mt] += cs[mt][nt][2] + cs[mt][nt][3];
            }
        }

        // ---- O += P @ V: each V fragment feeds both row blocks ----
        #pragma unroll
        for (int kk = 0; kk < 4; kk++) {
            uint32_t ap[2][4];
            #pragma unroll
            for (int mt = 0; mt < 2; mt++) {
                ap[mt][0] = pack_f16(__float2half_rn(cs[mt][2*kk][0]),
                                     __float2half_rn(cs[mt][2*kk][1]));
                ap[mt][1] = pack_f16(__float2half_rn(cs[mt][2*kk][2]),
                                     __float2half_rn(cs[mt][2*kk][3]));
                ap[mt][2] = pack_f16(__float2half_rn(cs[mt][2*kk+1][0]),
                                     __float2half_rn(cs[mt][2*kk+1][1]));
                ap[mt][3] = pack_f16(__float2half_rn(cs[mt][2*kk+1][2]),
                                     __float2half_rn(cs[mt][2*kk+1][3]));
            }
            const uint32_t koff = kk * 16 * APAD * 2;
            #pragma unroll
            for (int nto = 0; nto < 8; nto++) {
                uint32_t bh[2];
                LDMX2T(bh[0], bh[1], vbase + koff + nto * 16);
                mma_f16(o[0][nto], ap[0], bh);
                mma_f16(o[1][nto], ap[1], bh);
            }
        }

        __syncthreads();
        if (it + 2 < NKT) {
            attn_issue_kv(K16, V16, brow, hoff, (it + 2) * 64, sb, buf, tid);
            CP_COMMIT();
        }
    }

    // ---- row-sum reduction over t-lanes, finalize ----
    #pragma unroll
    for (int mt = 0; mt < 2; mt++) {
        l0[mt] += __shfl_xor_sync(0xFFFFFFFF, l0[mt], 1);
        l0[mt] += __shfl_xor_sync(0xFFFFFFFF, l0[mt], 2);
        l1[mt] += __shfl_xor_sync(0xFFFFFFFF, l1[mt], 1);
        l1[mt] += __shfl_xor_sync(0xFFFFFFFF, l1[mt], 2);
        float inv0 = 1.f / l0[mt], inv1 = 1.f / l1[mt];
        const size_t r0 = brow + q0 + wm + mt * 16 + g;
        #pragma unroll
        for (int nt = 0; nt < 8; nt++) {
            const int n = nt * 8 + 2 * t;
            uint32_t u0 = pack_f16(__float2half_rn(o[mt][nt][0] * inv0),
                                   __float2half_rn(o[mt][nt][1] * inv0));
            uint32_t u1 = pack_f16(__float2half_rn(o[mt][nt][2] * inv1),
                                   __float2half_rn(o[mt][nt][3] * inv1));
            *(uint32_t*)&O16[r0 * DD + hoff + n] = u0;
            *(uint32_t*)&O16[(r0 + 8) * DD + hoff + n] = u1;
        }
    }
}

// ---------------------------------------------------------------------------
extern "C" void kernel_launch(void* const* d_in, const int* in_sizes, int n_in,
                              void* d_out, int out_size)
{
    const float* x    = (const float*)d_in[0];
    const int*   mask = (const int*)  d_in[1];
    const float* Wq   = (const float*)d_in[2];
    const float* Wk   = (const float*)d_in[3];
    const float* Wv   = (const float*)d_in[4];
    const float* Wo   = (const float*)d_in[5];
    const float* bo   = (const float*)d_in[6];
    float* out = (float*)d_out;

    f16 *x16, *wq16, *wk16, *wv16, *wo16;
    f16 *q16, *k16, *v16, *a16;
    uint32_t* pmp;
    cudaGetSymbolAddress((void**)&x16, g_x16);
    cudaGetSymbolAddress((void**)&wq16, g_wq16); cudaGetSymbolAddress((void**)&wk16, g_wk16);
    cudaGetSymbolAddress((void**)&wv16, g_wv16); cudaGetSymbolAddress((void**)&wo16, g_wo16);
    cudaGetSymbolAddress((void**)&q16, g_q16);   cudaGetSymbolAddress((void**)&k16, g_k16);
    cudaGetSymbolAddress((void**)&v16, g_v16);   cudaGetSymbolAddress((void**)&a16, g_a16);
    cudaGetSymbolAddress((void**)&pmp, g_pm);

    cudaFuncSetAttribute(qkv_gemm, cudaFuncAttributeMaxDynamicSharedMemorySize, GEMM1_SMEM);
    cudaFuncSetAttribute(out_gemm, cudaFuncAttributeMaxDynamicSharedMemorySize, GEMM1_SMEM);
    cudaFuncSetAttribute(attn_kernel, cudaFuncAttributeMaxDynamicSharedMemorySize, ATTN_SMEM);

    split_all<<<(NSPLIT + 255) / 256, 256>>>(x, Wq, Wk, Wv, Wo,
                                             x16, wq16, wk16, wv16, wo16);
    pack_mask<<<(NMW + 255) / 256, 256>>>(mask, pmp);

    dim3 gq(DD / 128, MM / 128, 3);
    qkv_gemm<<<gq, 256, GEMM1_SMEM>>>(x16, wq16, wk16, wv16, q16, k16, v16);

    attn_kernel<<<dim3(SS / 128, HH, BB), 128, ATTN_SMEM>>>(
        q16, k16, v16, pmp, a16);

    dim3 go(DD / 128, MM / 128);
    out_gemm<<<go, 256, GEMM1_SMEM>>>(a16, wo16, bo, out);
}

// round 14
// speedup vs baseline: 1.5618x; 1.5618x over previous
#include <cuda_runtime.h>
#include <cuda_fp16.h>
#include <math.h>
#include <stdint.h>

#define BB 2
#define SS 2048
#define DD 1024
#define HH 16
#define HDIM 64
#define MM (BB*SS)

typedef __half f16;

// ---------------------------------------------------------------------------
// Scratch (__device__ globals; no runtime allocation)
// ---------------------------------------------------------------------------
__device__ f16 g_x16[MM*DD];
__device__ f16 g_wq16[DD*DD], g_wk16[DD*DD], g_wv16[DD*DD], g_wo16[DD*DD];
__device__ f16 g_q16[MM*DD], g_k16[MM*DD], g_v16[MM*DD], g_a16[MM*DD];
#define NMW (BB * SS * (SS / 32))
__device__ uint32_t g_pm[NMW];

// ---------------------------------------------------------------------------
// Helpers
// ---------------------------------------------------------------------------
__device__ __forceinline__ uint32_t pack_f16(f16 a, f16 b) {
    __half2 t = __halves2half2(a, b);
    return *reinterpret_cast<uint32_t*>(&t);
}

__device__ __forceinline__ void mma_f16(float* c, const uint32_t* a, const uint32_t* b) {
    asm volatile(
        "mma.sync.aligned.m16n8k16.row.col.f32.f16.f16.f32 "
        "{%0,%1,%2,%3}, {%4,%5,%6,%7}, {%8,%9}, {%0,%1,%2,%3};\n"
        : "+f"(c[0]), "+f"(c[1]), "+f"(c[2]), "+f"(c[3])
        : "r"(a[0]), "r"(a[1]), "r"(a[2]), "r"(a[3]), "r"(b[0]), "r"(b[1]));
}

__device__ __forceinline__ uint32_t smem_u32(const void* p) {
    return (uint32_t)__cvta_generic_to_shared(p);
}

#define CP16(sa, gp) \
    asm volatile("cp.async.cg.shared.global [%0], [%1], 16;\n" :: "r"(sa), "l"(gp))
#define CP_COMMIT() asm volatile("cp.async.commit_group;\n" ::: "memory")
template<int N>
__device__ __forceinline__ void cp_wait() {
    asm volatile("cp.async.wait_group %0;\n" :: "n"(N) : "memory");
}

#define LDMX4T(r0, r1, r2, r3, addr) \
    asm volatile("ldmatrix.sync.aligned.m8n8.x4.trans.shared.b16 {%0,%1,%2,%3}, [%4];\n" \
                 : "=r"(r0), "=r"(r1), "=r"(r2), "=r"(r3) : "r"(addr))
#define LDMX4(r0, r1, r2, r3, addr) \
    asm volatile("ldmatrix.sync.aligned.m8n8.x4.shared.b16 {%0,%1,%2,%3}, [%4];\n" \
                 : "=r"(r0), "=r"(r1), "=r"(r2), "=r"(r3) : "r"(addr))

// softmax in exp2 domain: 0.125 * log2(e), folded into q at qkv epilogue
#define SCL2 0.18033688011112042f

// ---------------------------------------------------------------------------
// Convert kernel: x, Wq, Wk, Wv, Wo -> single fp16
// ---------------------------------------------------------------------------
#define NX4 (MM * DD / 4)
#define NW4 (DD * DD / 4)
#define NSPLIT (NX4 + 4 * NW4)

__global__ void split_all(const float* __restrict__ x,
                          const float* __restrict__ wq, const float* __restrict__ wk,
                          const float* __restrict__ wv, const float* __restrict__ wo,
                          f16* __restrict__ x16,
                          f16* __restrict__ wq16, f16* __restrict__ wk16,
                          f16* __restrict__ wv16, f16* __restrict__ wo16) {
    int i = blockIdx.x * blockDim.x + threadIdx.x;
    if (i >= NSPLIT) return;
    const float* s; f16* d; int off;
    if (i < NX4)                { s = x;  d = x16;  off = i; }
    else if (i < NX4 + NW4)     { s = wq; d = wq16; off = i - NX4; }
    else if (i < NX4 + 2 * NW4) { s = wk; d = wk16; off = i - NX4 - NW4; }
    else if (i < NX4 + 3 * NW4) { s = wv; d = wv16; off = i - NX4 - 2 * NW4; }
    else                        { s = wo; d = wo16; off = i - NX4 - 3 * NW4; }
    float4 v = ((const float4*)s)[off];
    uint2 u;
    u.x = pack_f16(__float2half_rn(v.x), __float2half_rn(v.y));
    u.y = pack_f16(__float2half_rn(v.z), __float2half_rn(v.w));
    ((uint2*)d)[off] = u;
}

// ---------------------------------------------------------------------------
// Mask pack: int32 (0/1) -> 1 bit per element
// ---------------------------------------------------------------------------
__global__ void pack_mask(const int* __restrict__ mask, uint32_t* __restrict__ pm) {
    int w = blockIdx.x * blockDim.x + threadIdx.x;
    if (w >= NMW) return;
    const int4* src = (const int4*)(mask + (size_t)w * 32);
    uint32_t bits = 0;
    #pragma unroll
    for (int j = 0; j < 8; j++) {
        int4 m = src[j];
        bits |= (uint32_t)(m.x == 1) << (4 * j);
        bits |= (uint32_t)(m.y == 1) << (4 * j + 1);
        bits |= (uint32_t)(m.z == 1) << (4 * j + 2);
        bits |= (uint32_t)(m.w == 1) << (4 * j + 3);
    }
    pm[w] = bits;
}

// ---------------------------------------------------------------------------
// fp16 single-pass GEMM: 128x128 CTA tile, 8 warps (4M x 2N, 32x64 warp tile),
// 3-stage cp.async. (unchanged from R12)
// ---------------------------------------------------------------------------
#define GKC 32
#define GPAD 40
#define GA_ELE (128 * GPAD)
#define GB_ELE (128 * GPAD)
#define G1STG (GA_ELE + GB_ELE)
#define G1O_WH GA_ELE
#define GEMM1_SMEM (3 * G1STG * 2)

__device__ __forceinline__ void gemm1_issue(const f16* __restrict__ A,
                                            const f16* __restrict__ W,
                                            int m0, int n0, int kt,
                                            uint32_t sbase, int tid) {
    #pragma unroll
    for (int j = 0; j < 2; j++) {
        int cidx = tid + 256 * j;
        int row = cidx >> 2, col = (cidx & 3) * 8;
        uint32_t so = sbase + (row * GPAD + col) * 2;
        CP16(so, A + (size_t)(m0 + row) * DD + kt + col);
    }
    #pragma unroll
    for (int j = 0; j < 2; j++) {
        int cidx = tid + 256 * j;
        int row = cidx >> 2, col = (cidx & 3) * 8;
        uint32_t so = sbase + (G1O_WH + row * GPAD + col) * 2;
        CP16(so, W + (size_t)(n0 + row) * DD + kt + col);
    }
}

__device__ __forceinline__ void gemm1_main(const f16* __restrict__ A,
                                           const f16* __restrict__ W,
                                           int m0, int n0,
                                           float c[2][8][4]) {
    extern __shared__ f16 sm16[];
    const uint32_t sb = smem_u32(sm16);
    const int tid = threadIdx.x;
    const int wid = tid >> 5, lane = tid & 31;
    const int wm = (wid >> 1) * 32, wn = (wid & 1) * 64;
    const int a_lm = (lane & 15) * GPAD + (lane >> 4) * 8;
    const int b_lm = (wn + (lane >> 4) * 8 + (lane & 7)) * GPAD + ((lane >> 3) & 1) * 8;

    gemm1_issue(A, W, m0, n0, 0,   sb,             tid); CP_COMMIT();
    gemm1_issue(A, W, m0, n0, GKC, sb + G1STG * 2, tid); CP_COMMIT();

    const int NCH = DD / GKC;
    for (int ch = 0; ch < NCH; ch++) {
        if (ch + 2 < NCH)
            gemm1_issue(A, W, m0, n0, (ch + 2) * GKC,
                        sb + ((ch + 2) % 3) * G1STG * 2, tid);
        CP_COMMIT();
        cp_wait<2>();
        __syncthreads();

        const uint32_t sA = sb + ((ch % 3) * G1STG) * 2;

        #pragma unroll
        for (int ks = 0; ks < 2; ks++) {
            const int k0 = ks * 16;
            uint32_t ah[2][4];
            #pragma unroll
            for (int mt = 0; mt < 2; mt++) {
                uint32_t ad = sA + (uint32_t)((wm + mt * 16) * GPAD + a_lm + k0) * 2;
                LDMX4(ah[mt][0], ah[mt][1], ah[mt][2], ah[mt][3], ad);
            }
            #pragma unroll
            for (int j = 0; j < 4; j++) {
                uint32_t bd = sA + (uint32_t)(G1O_WH + 2 * j * 8 * GPAD + b_lm + k0) * 2;
                uint32_t bh[4];
                LDMX4(bh[0], bh[1], bh[2], bh[3], bd);
                #pragma unroll
                for (int sub = 0; sub < 2; sub++) {
                    const int nt = 2 * j + sub;
                    #pragma unroll
                    for (int mt = 0; mt < 2; mt++)
                        mma_f16(c[mt][nt], ah[mt], &bh[2 * sub]);
                }
            }
        }
        __syncthreads();
    }
}

__global__ void __launch_bounds__(256, 2)
qkv_gemm(const f16* __restrict__ x16,
         const f16* __restrict__ wq16, const f16* __restrict__ wk16,
         const f16* __restrict__ wv16,
         f16* __restrict__ q16, f16* __restrict__ k16, f16* __restrict__ v16) {
    const int z = blockIdx.z;
    const f16* Wh = (z == 0) ? wq16 : (z == 1) ? wk16 : wv16;
    f16* Y = (z == 0) ? q16 : (z == 1) ? k16 : v16;
    const int m0 = blockIdx.y * 128, n0 = blockIdx.x * 128;
    const int tid = threadIdx.x;
    const int wid = tid >> 5, lane = tid & 31;
    const int g = lane >> 2, t = lane & 3;
    const int wm = (wid >> 1) * 32, wn = (wid & 1) * 64;

    float c[2][8][4] = {};
    gemm1_main(x16, Wh, m0, n0, c);

    // q pre-scaled by SCL2 (softmax exp2-domain fold); k, v unscaled
    const float qs = (z == 0) ? SCL2 : 1.0f;

    #pragma unroll
    for (int mt = 0; mt < 2; mt++) {
        const int r = m0 + wm + mt * 16 + g;
        #pragma unroll
        for (int nt = 0; nt < 8; nt++) {
            const int n = n0 + wn + nt * 8 + 2 * t;
            uint32_t u0 = pack_f16(__float2half_rn(c[mt][nt][0] * qs),
                                   __float2half_rn(c[mt][nt][1] * qs));
            uint32_t u1 = pack_f16(__float2half_rn(c[mt][nt][2] * qs),
                                   __float2half_rn(c[mt][nt][3] * qs));
            *(uint32_t*)&Y[(size_t)r * DD + n] = u0;
            *(uint32_t*)&Y[(size_t)(r + 8) * DD + n] = u1;
        }
    }
}

__global__ void __launch_bounds__(256, 2)
out_gemm(const f16* __restrict__ a16, const f16* __restrict__ wo16,
         const float* __restrict__ bo, float* __restrict__ out) {
    const int m0 = blockIdx.y * 128, n0 = blockIdx.x * 128;
    const int tid = threadIdx.x;
    const int wid = tid >> 5, lane = tid & 31;
    const int g = lane >> 2, t = lane & 3;
    const int wm = (wid >> 1) * 32, wn = (wid & 1) * 64;

    float c[2][8][4] = {};
    gemm1_main(a16, wo16, m0, n0, c);

    #pragma unroll
    for (int mt = 0; mt < 2; mt++) {
        const int r = m0 + wm + mt * 16 + g;
        #pragma unroll
        for (int nt = 0; nt < 8; nt++) {
            const int n = n0 + wn + nt * 8 + 2 * t;
            float bx = bo[n], by = bo[n + 1];
            float2 o0 = { c[mt][nt][0] + bx, c[mt][nt][1] + by };
            float2 o1 = { c[mt][nt][2] + bx, c[mt][nt][3] + by };
            *(float2*)&out[(size_t)r * DD + n] = o0;
            *(float2*)&out[(size_t)(r + 8) * DD + n] = o1;
        }
    }
}

// ---------------------------------------------------------------------------
// Flash attention (R12 structure): 64 q-rows/CTA, 4 warps x 16 rows,
// fp16 1-pass MMAs, no-max exp2 softmax (q pre-scaled), double-buffered KV,
// packed mask (loads hoisted), V fragments via ldmatrix.x4.trans.
// 128 threads, 3 CTAs/SM.
// ---------------------------------------------------------------------------
#define APAD 72
#define AT_ELE (64 * APAD)
#define AO_Q 0
#define AO_K(s) ((1 + 2 * (s)) * AT_ELE)
#define AO_V(s) ((2 + 2 * (s)) * AT_ELE)
#define ATTN_SMEM (5 * AT_ELE * 2)

__device__ __forceinline__ void attn_issue_kv(const f16* __restrict__ K16,
                                              const f16* __restrict__ V16,
                                              size_t brow, size_t hoff, int kt,
                                              uint32_t sb, int s, int tid) {
    #pragma unroll
    for (int j = 0; j < 4; j++) {
        int cidx = tid + 128 * j;
        int row = cidx >> 3, col = (cidx & 7) * 8;
        uint32_t so = sb + (AO_K(s) + row * APAD + col) * 2;
        size_t go = (brow + kt + row) * DD + hoff + col;
        CP16(so,              K16 + go);
        CP16(so + AT_ELE * 2, V16 + go);
    }
}

__global__ void __launch_bounds__(128, 3)
attn_kernel(const f16* __restrict__ Q16,
            const f16* __restrict__ K16, const f16* __restrict__ V16,
            const uint32_t* __restrict__ pm,
            f16* __restrict__ O16)
{
    extern __shared__ f16 smA[];
    const uint32_t sb = smem_u32(smA);
    const int tid = threadIdx.x;
    const int wid = tid >> 5, lane = tid & 31;
    const int g = lane >> 2, t = lane & 3;
    const int q0 = blockIdx.x * 64;
    const int h = blockIdx.y;
    const int b = blockIdx.z;
    const int wm = wid * 16;

    const size_t hoff = (size_t)h * HDIM;
    const size_t brow = (size_t)b * SS;

    #pragma unroll
    for (int j = 0; j < 4; j++) {
        int cidx = tid + 128 * j;
        int row = cidx >> 3, col = (cidx & 7) * 8;
        uint32_t so = sb + (AO_Q + row * APAD + col) * 2;
        CP16(so, Q16 + (brow + q0 + row) * DD + hoff + col);
    }
    CP_COMMIT();
    attn_issue_kv(K16, V16, brow, hoff, 0,  sb, 0, tid); CP_COMMIT();
    attn_issue_kv(K16, V16, brow, hoff, 64, sb, 1, tid); CP_COMMIT();

    cp_wait<2>();
    __syncthreads();

    uint32_t aq[4][4];
    {
        const int a_lm = (lane & 15) * APAD + (lane >> 4) * 8;
        #pragma unroll
        for (int kk = 0; kk < 4; kk++) {
            uint32_t ad = sb + (uint32_t)(AO_Q + wm * APAD + a_lm + kk * 16) * 2;
            LDMX4(aq[kk][0], aq[kk][1], aq[kk][2], aq[kk][3], ad);
        }
    }

    float o[8][4] = {};
    float l0r = 0.f, l1r = 0.f;
    const int mrow0 = q0 + wm + g;
    const int NKT = SS / 64;

    const int k_lm = ((lane >> 4) * 8 + (lane & 7)) * APAD + ((lane >> 3) & 1) * 8;
    // V x4.trans lane mapping: lanes 0-15 -> 16 k-rows at col block nto,
    // lanes 16-31 -> same rows at col block nto+1 (next 16 bytes).
    const int v_lm = (lane & 15) * APAD + (lane >> 4) * 8;
    const uint32_t* pr0 = pm + (brow + mrow0) * (SS / 32);
    const uint32_t* pr1 = pr0 + 8 * (SS / 32);
    const int s0 = 2 * t;

    for (int it = 0; it < NKT; it++) {
        // Hoist mask words: gmem latency hides under the S MMAs below
        uint2 w0 = *(const uint2*)(pr0 + it * 2);
        uint2 w1 = *(const uint2*)(pr1 + it * 2);

        cp_wait<1>();
        __syncthreads();

        const int buf = it & 1;
        const uint32_t kbase = sb + (uint32_t)AO_K(buf) * 2;
        const uint32_t vbase = sb + (uint32_t)(AO_V(buf) + v_lm) * 2;

        // ---- S = Q @ K^T (fp16 1-pass) ----
        float cs[8][4] = {};
        #pragma unroll
        for (int kk = 0; kk < 4; kk++) {
            const int k0 = kk * 16;
            #pragma unroll
            for (int j = 0; j < 4; j++) {
                uint32_t kd = kbase + (uint32_t)(2 * j * 8 * APAD + k_lm + k0) * 2;
                uint32_t bh[4];
                LDMX4(bh[0], bh[1], bh[2], bh[3], kd);
                mma_f16(cs[2 * j],     aq[kk], &bh[0]);
                mma_f16(cs[2 * j + 1], aq[kk], &bh[2]);
            }
        }

        // ---- P = exp2(S) (q pre-scaled), masked -> 0; accumulate row sums ----
        #pragma unroll
        for (int nt = 0; nt < 8; nt++) {
            const uint32_t wa = (nt < 4) ? w0.x : w0.y;
            const uint32_t wb = (nt < 4) ? w1.x : w1.y;
            const int p = 8 * (nt & 3) + s0;
            float e0 = exp2f(cs[nt][0]);
            float e1 = exp2f(cs[nt][1]);
            float e2 = exp2f(cs[nt][2]);
            float e3 = exp2f(cs[nt][3]);
            cs[nt][0] = ((wa >> p) & 1)       ? 0.f : e0;
            cs[nt][1] = ((wa >> (p + 1)) & 1) ? 0.f : e1;
            cs[nt][2] = ((wb >> p) & 1)       ? 0.f : e2;
            cs[nt][3] = ((wb >> (p + 1)) & 1) ? 0.f : e3;
            l0r += cs[nt][0] + cs[nt][1];
            l1r += cs[nt][2] + cs[nt][3];
        }

        // ---- O += P @ V (fp16 1-pass), V via ldmatrix.x4.trans ----
        #pragma unroll
        for (int kk = 0; kk < 4; kk++) {
            uint32_t ap[4];
            ap[0] = pack_f16(__float2half_rn(cs[2*kk][0]),   __float2half_rn(cs[2*kk][1]));
            ap[1] = pack_f16(__float2half_rn(cs[2*kk][2]),   __float2half_rn(cs[2*kk][3]));
            ap[2] = pack_f16(__float2half_rn(cs[2*kk+1][0]), __float2half_rn(cs[2*kk+1][1]));
            ap[3] = pack_f16(__float2half_rn(cs[2*kk+1][2]), __float2half_rn(cs[2*kk+1][3]));
            const uint32_t koff = kk * 16 * APAD * 2;
            #pragma unroll
            for (int np = 0; np < 4; np++) {   // pairs of nto
                uint32_t bh[4];
                LDMX4T(bh[0], bh[1], bh[2], bh[3], vbase + koff + np * 32);
                mma_f16(o[2 * np],     ap, &bh[0]);
                mma_f16(o[2 * np + 1], ap, &bh[2]);
            }
        }

        __syncthreads();
        if (it + 2 < NKT) {
            attn_issue_kv(K16, V16, brow, hoff, (it + 2) * 64, sb, buf, tid);
            CP_COMMIT();
        }
    }

    // ---- single row-sum reduction over t-lanes ----
    l0r += __shfl_xor_sync(0xFFFFFFFF, l0r, 1);
    l0r += __shfl_xor_sync(0xFFFFFFFF, l0r, 2);
    l1r += __shfl_xor_sync(0xFFFFFFFF, l1r, 1);
    l1r += __shfl_xor_sync(0xFFFFFFFF, l1r, 2);

    float inv0 = 1.f / l0r, inv1 = 1.f / l1r;
    const size_t r0 = brow + q0 + wm + g;
    #pragma unroll
    for (int nt = 0; nt < 8; nt++) {
        const int n = nt * 8 + 2 * t;
        uint32_t u0 = pack_f16(__float2half_rn(o[nt][0] * inv0),
                               __float2half_rn(o[nt][1] * inv0));
        uint32_t u1 = pack_f16(__float2half_rn(o[nt][2] * inv1),
                               __float2half_rn(o[nt][3] * inv1));
        *(uint32_t*)&O16[r0 * DD + hoff + n] = u0;
        *(uint32_t*)&O16[(r0 + 8) * DD + hoff + n] = u1;
    }
}

// ---------------------------------------------------------------------------
extern "C" void kernel_launch(void* const* d_in, const int* in_sizes, int n_in,
                              void* d_out, int out_size)
{
    const float* x    = (const float*)d_in[0];
    const int*   mask = (const int*)  d_in[1];
    const float* Wq   = (const float*)d_in[2];
    const float* Wk   = (const float*)d_in[3];
    const float* Wv   = (const float*)d_in[4];
    const float* Wo   = (const float*)d_in[5];
    const float* bo   = (const float*)d_in[6];
    float* out = (float*)d_out;

    f16 *x16, *wq16, *wk16, *wv16, *wo16;
    f16 *q16, *k16, *v16, *a16;
    uint32_t* pmp;
    cudaGetSymbolAddress((void**)&x16, g_x16);
    cudaGetSymbolAddress((void**)&wq16, g_wq16); cudaGetSymbolAddress((void**)&wk16, g_wk16);
    cudaGetSymbolAddress((void**)&wv16, g_wv16); cudaGetSymbolAddress((void**)&wo16, g_wo16);
    cudaGetSymbolAddress((void**)&q16, g_q16);   cudaGetSymbolAddress((void**)&k16, g_k16);
    cudaGetSymbolAddress((void**)&v16, g_v16);   cudaGetSymbolAddress((void**)&a16, g_a16);
    cudaGetSymbolAddress((void**)&pmp, g_pm);

    cudaFuncSetAttribute(qkv_gemm, cudaFuncAttributeMaxDynamicSharedMemorySize, GEMM1_SMEM);
    cudaFuncSetAttribute(out_gemm, cudaFuncAttributeMaxDynamicSharedMemorySize, GEMM1_SMEM);
    cudaFuncSetAttribute(attn_kernel, cudaFuncAttributeMaxDynamicSharedMemorySize, ATTN_SMEM);

    split_all<<<(NSPLIT + 255) / 256, 256>>>(x, Wq, Wk, Wv, Wo,
                                             x16, wq16, wk16, wv16, wo16);
    pack_mask<<<(NMW + 255) / 256, 256>>>(mask, pmp);

    dim3 gq(DD / 128, MM / 128, 3);
    qkv_gemm<<<gq, 256, GEMM1_SMEM>>>(x16, wq16, wk16, wv16, q16, k16, v16);

    attn_kernel<<<dim3(SS / 64, HH, BB), 128, ATTN_SMEM>>>(
        q16, k16, v16, pmp, a16);

    dim3 go(DD / 128, MM / 128);
    out_gemm<<<go, 256, GEMM1_SMEM>>>(a16, wo16, bo, out);
}

// round 15
// speedup vs baseline: 1.6345x; 1.0466x over previous
#include <cuda_runtime.h>
#include <cuda_fp16.h>
#include <math.h>
#include <stdint.h>

#define BB 2
#define SS 2048
#define DD 1024
#define HH 16
#define HDIM 64
#define MM (BB*SS)

typedef __half f16;

// ---------------------------------------------------------------------------
// Scratch (__device__ globals; no runtime allocation)
// ---------------------------------------------------------------------------
__device__ f16 g_x16[MM*DD];
__device__ f16 g_wq16[DD*DD], g_wk16[DD*DD], g_wv16[DD*DD], g_wo16[DD*DD];
__device__ f16 g_q16[MM*DD], g_k16[MM*DD], g_v16[MM*DD], g_a16[MM*DD];
#define NMW (BB * SS * (SS / 32))
__device__ uint32_t g_pm[NMW];

// ---------------------------------------------------------------------------
// Helpers
// ---------------------------------------------------------------------------
__device__ __forceinline__ uint32_t pack_f16(f16 a, f16 b) {
    __half2 t = __halves2half2(a, b);
    return *reinterpret_cast<uint32_t*>(&t);
}

__device__ __forceinline__ float ex2(float x) {
    float r;
    asm("ex2.approx.ftz.f32 %0, %1;" : "=f"(r) : "f"(x));
    return r;
}

__device__ __forceinline__ void mma_f16(float* c, const uint32_t* a, const uint32_t* b) {
    asm volatile(
        "mma.sync.aligned.m16n8k16.row.col.f32.f16.f16.f32 "
        "{%0,%1,%2,%3}, {%4,%5,%6,%7}, {%8,%9}, {%0,%1,%2,%3};\n"
        : "+f"(c[0]), "+f"(c[1]), "+f"(c[2]), "+f"(c[3])
        : "r"(a[0]), "r"(a[1]), "r"(a[2]), "r"(a[3]), "r"(b[0]), "r"(b[1]));
}

__device__ __forceinline__ uint32_t smem_u32(const void* p) {
    return (uint32_t)__cvta_generic_to_shared(p);
}

#define CP16(sa, gp) \
    asm volatile("cp.async.cg.shared.global [%0], [%1], 16;\n" :: "r"(sa), "l"(gp))
#define CP_COMMIT() asm volatile("cp.async.commit_group;\n" ::: "memory")
template<int N>
__device__ __forceinline__ void cp_wait() {
    asm volatile("cp.async.wait_group %0;\n" :: "n"(N) : "memory");
}

#define LDMX4T(r0, r1, r2, r3, addr) \
    asm volatile("ldmatrix.sync.aligned.m8n8.x4.trans.shared.b16 {%0,%1,%2,%3}, [%4];\n" \
                 : "=r"(r0), "=r"(r1), "=r"(r2), "=r"(r3) : "r"(addr))
#define LDMX4(r0, r1, r2, r3, addr) \
    asm volatile("ldmatrix.sync.aligned.m8n8.x4.shared.b16 {%0,%1,%2,%3}, [%4];\n" \
                 : "=r"(r0), "=r"(r1), "=r"(r2), "=r"(r3) : "r"(addr))

// softmax in exp2 domain: 0.125 * log2(e), folded into q at qkv epilogue
#define SCL2 0.18033688011112042f

// ---------------------------------------------------------------------------
// Fused prep kernel: fp32->fp16 conversions + 1-bit mask pack, one launch
// ---------------------------------------------------------------------------
#define NX4 (MM * DD / 4)
#define NW4 (DD * DD / 4)
#define NSPLIT (NX4 + 4 * NW4)
#define NPREP (NSPLIT + NMW)

__global__ void prep_all(const float* __restrict__ x,
                         const float* __restrict__ wq, const float* __restrict__ wk,
                         const float* __restrict__ wv, const float* __restrict__ wo,
                         const int* __restrict__ mask,
                         f16* __restrict__ x16,
                         f16* __restrict__ wq16, f16* __restrict__ wk16,
                         f16* __restrict__ wv16, f16* __restrict__ wo16,
                         uint32_t* __restrict__ pm) {
    int i = blockIdx.x * blockDim.x + threadIdx.x;
    if (i >= NPREP) return;
    if (i < NSPLIT) {
        const float* s; f16* d; int off;
        if (i < NX4)                { s = x;  d = x16;  off = i; }
        else if (i < NX4 + NW4)     { s = wq; d = wq16; off = i - NX4; }
        else if (i < NX4 + 2 * NW4) { s = wk; d = wk16; off = i - NX4 - NW4; }
        else if (i < NX4 + 3 * NW4) { s = wv; d = wv16; off = i - NX4 - 2 * NW4; }
        else                        { s = wo; d = wo16; off = i - NX4 - 3 * NW4; }
        float4 v = ((const float4*)s)[off];
        uint2 u;
        u.x = pack_f16(__float2half_rn(v.x), __float2half_rn(v.y));
        u.y = pack_f16(__float2half_rn(v.z), __float2half_rn(v.w));
        ((uint2*)d)[off] = u;
    } else {
        int w = i - NSPLIT;
        const int4* src = (const int4*)(mask + (size_t)w * 32);
        uint32_t bits = 0;
        #pragma unroll
        for (int j = 0; j < 8; j++) {
            int4 m = src[j];
            bits |= (uint32_t)(m.x == 1) << (4 * j);
            bits |= (uint32_t)(m.y == 1) << (4 * j + 1);
            bits |= (uint32_t)(m.z == 1) << (4 * j + 2);
            bits |= (uint32_t)(m.w == 1) << (4 * j + 3);
        }
        pm[w] = bits;
    }
}

// ---------------------------------------------------------------------------
// fp16 single-pass GEMM: 128x128 CTA tile, 8 warps (4M x 2N, 32x64 warp tile),
// 3-stage cp.async.
// ---------------------------------------------------------------------------
#define GKC 32
#define GPAD 40
#define GA_ELE (128 * GPAD)
#define GB_ELE (128 * GPAD)
#define G1STG (GA_ELE + GB_ELE)
#define G1O_WH GA_ELE
#define GEMM1_SMEM (3 * G1STG * 2)

__device__ __forceinline__ void gemm1_issue(const f16* __restrict__ A,
                                            const f16* __restrict__ W,
                                            int m0, int n0, int kt,
                                            uint32_t sbase, int tid) {
    #pragma unroll
    for (int j = 0; j < 2; j++) {
        int cidx = tid + 256 * j;
        int row = cidx >> 2, col = (cidx & 3) * 8;
        uint32_t so = sbase + (row * GPAD + col) * 2;
        CP16(so, A + (size_t)(m0 + row) * DD + kt + col);
    }
    #pragma unroll
    for (int j = 0; j < 2; j++) {
        int cidx = tid + 256 * j;
        int row = cidx >> 2, col = (cidx & 3) * 8;
        uint32_t so = sbase + (G1O_WH + row * GPAD + col) * 2;
        CP16(so, W + (size_t)(n0 + row) * DD + kt + col);
    }
}

__device__ __forceinline__ void gemm1_main(const f16* __restrict__ A,
                                           const f16* __restrict__ W,
                                           int m0, int n0,
                                           float c[2][8][4]) {
    extern __shared__ f16 sm16[];
    const uint32_t sb = smem_u32(sm16);
    const int tid = threadIdx.x;
    const int wid = tid >> 5, lane = tid & 31;
    const int wm = (wid >> 1) * 32, wn = (wid & 1) * 64;
    const int a_lm = (lane & 15) * GPAD + (lane >> 4) * 8;
    const int b_lm = (wn + (lane >> 4) * 8 + (lane & 7)) * GPAD + ((lane >> 3) & 1) * 8;

    gemm1_issue(A, W, m0, n0, 0,   sb,             tid); CP_COMMIT();
    gemm1_issue(A, W, m0, n0, GKC, sb + G1STG * 2, tid); CP_COMMIT();

    const int NCH = DD / GKC;
    for (int ch = 0; ch < NCH; ch++) {
        if (ch + 2 < NCH)
            gemm1_issue(A, W, m0, n0, (ch + 2) * GKC,
                        sb + ((ch + 2) % 3) * G1STG * 2, tid);
        CP_COMMIT();
        cp_wait<2>();
        __syncthreads();

        const uint32_t sA = sb + ((ch % 3) * G1STG) * 2;

        #pragma unroll
        for (int ks = 0; ks < 2; ks++) {
            const int k0 = ks * 16;
            uint32_t ah[2][4];
            #pragma unroll
            for (int mt = 0; mt < 2; mt++) {
                uint32_t ad = sA + (uint32_t)((wm + mt * 16) * GPAD + a_lm + k0) * 2;
                LDMX4(ah[mt][0], ah[mt][1], ah[mt][2], ah[mt][3], ad);
            }
            #pragma unroll
            for (int j = 0; j < 4; j++) {
                uint32_t bd = sA + (uint32_t)(G1O_WH + 2 * j * 8 * GPAD + b_lm + k0) * 2;
                uint32_t bh[4];
                LDMX4(bh[0], bh[1], bh[2], bh[3], bd);
                #pragma unroll
                for (int sub = 0; sub < 2; sub++) {
                    const int nt = 2 * j + sub;
                    #pragma unroll
                    for (int mt = 0; mt < 2; mt++)
                        mma_f16(c[mt][nt], ah[mt], &bh[2 * sub]);
                }
            }
        }
        __syncthreads();
    }
}

__global__ void __launch_bounds__(256, 2)
qkv_gemm(const f16* __restrict__ x16,
         const f16* __restrict__ wq16, const f16* __restrict__ wk16,
         const f16* __restrict__ wv16,
         f16* __restrict__ q16, f16* __restrict__ k16, f16* __restrict__ v16) {
    const int z = blockIdx.z;
    const f16* Wh = (z == 0) ? wq16 : (z == 1) ? wk16 : wv16;
    f16* Y = (z == 0) ? q16 : (z == 1) ? k16 : v16;
    const int m0 = blockIdx.y * 128, n0 = blockIdx.x * 128;
    const int tid = threadIdx.x;
    const int wid = tid >> 5, lane = tid & 31;
    const int g = lane >> 2, t = lane & 3;
    const int wm = (wid >> 1) * 32, wn = (wid & 1) * 64;

    float c[2][8][4] = {};
    gemm1_main(x16, Wh, m0, n0, c);

    // q pre-scaled by SCL2 (softmax exp2-domain fold); k, v unscaled
    const float qs = (z == 0) ? SCL2 : 1.0f;

    #pragma unroll
    for (int mt = 0; mt < 2; mt++) {
        const int r = m0 + wm + mt * 16 + g;
        #pragma unroll
        for (int nt = 0; nt < 8; nt++) {
            const int n = n0 + wn + nt * 8 + 2 * t;
            uint32_t u0 = pack_f16(__float2half_rn(c[mt][nt][0] * qs),
                                   __float2half_rn(c[mt][nt][1] * qs));
            uint32_t u1 = pack_f16(__float2half_rn(c[mt][nt][2] * qs),
                                   __float2half_rn(c[mt][nt][3] * qs));
            *(uint32_t*)&Y[(size_t)r * DD + n] = u0;
            *(uint32_t*)&Y[(size_t)(r + 8) * DD + n] = u1;
        }
    }
}

__global__ void __launch_bounds__(256, 2)
out_gemm(const f16* __restrict__ a16, const f16* __restrict__ wo16,
         const float* __restrict__ bo, float* __restrict__ out) {
    const int m0 = blockIdx.y * 128, n0 = blockIdx.x * 128;
    const int tid = threadIdx.x;
    const int wid = tid >> 5, lane = tid & 31;
    const int g = lane >> 2, t = lane & 3;
    const int wm = (wid >> 1) * 32, wn = (wid & 1) * 64;

    float c[2][8][4] = {};
    gemm1_main(a16, wo16, m0, n0, c);

    #pragma unroll
    for (int mt = 0; mt < 2; mt++) {
        const int r = m0 + wm + mt * 16 + g;
        #pragma unroll
        for (int nt = 0; nt < 8; nt++) {
            const int n = n0 + wn + nt * 8 + 2 * t;
            float bx = bo[n], by = bo[n + 1];
            float2 o0 = { c[mt][nt][0] + bx, c[mt][nt][1] + by };
            float2 o1 = { c[mt][nt][2] + bx, c[mt][nt][3] + by };
            *(float2*)&out[(size_t)r * DD + n] = o0;
            *(float2*)&out[(size_t)(r + 8) * DD + n] = o1;
        }
    }
}

// ---------------------------------------------------------------------------
// Flash attention: 64 q-rows/CTA, 4 warps x 16 rows, fp16 1-pass MMAs,
// no-max exp2 softmax via MUFU.EX2 (q pre-scaled), double-buffered KV,
// packed mask (hoisted loads), V via ldmatrix.x4.trans. 128 thr, 3 CTAs/SM.
// ---------------------------------------------------------------------------
#define APAD 72
#define AT_ELE (64 * APAD)
#define AO_Q 0
#define AO_K(s) ((1 + 2 * (s)) * AT_ELE)
#define AO_V(s) ((2 + 2 * (s)) * AT_ELE)
#define ATTN_SMEM (5 * AT_ELE * 2)

__device__ __forceinline__ void attn_issue_kv(const f16* __restrict__ K16,
                                              const f16* __restrict__ V16,
                                              size_t brow, size_t hoff, int kt,
                                              uint32_t sb, int s, int tid) {
    #pragma unroll
    for (int j = 0; j < 4; j++) {
        int cidx = tid + 128 * j;
        int row = cidx >> 3, col = (cidx & 7) * 8;
        uint32_t so = sb + (AO_K(s) + row * APAD + col) * 2;
        size_t go = (brow + kt + row) * DD + hoff + col;
        CP16(so,              K16 + go);
        CP16(so + AT_ELE * 2, V16 + go);
    }
}

__global__ void __launch_bounds__(128, 3)
attn_kernel(const f16* __restrict__ Q16,
            const f16* __restrict__ K16, const f16* __restrict__ V16,
            const uint32_t* __restrict__ pm,
            f16* __restrict__ O16)
{
    extern __shared__ f16 smA[];
    const uint32_t sb = smem_u32(smA);
    const int tid = threadIdx.x;
    const int wid = tid >> 5, lane = tid & 31;
    const int g = lane >> 2, t = lane & 3;
    const int q0 = blockIdx.x * 64;
    const int h = blockIdx.y;
    const int b = blockIdx.z;
    const int wm = wid * 16;

    const size_t hoff = (size_t)h * HDIM;
    const size_t brow = (size_t)b * SS;

    #pragma unroll
    for (int j = 0; j < 4; j++) {
        int cidx = tid + 128 * j;
        int row = cidx >> 3, col = (cidx & 7) * 8;
        uint32_t so = sb + (AO_Q + row * APAD + col) * 2;
        CP16(so, Q16 + (brow + q0 + row) * DD + hoff + col);
    }
    CP_COMMIT();
    attn_issue_kv(K16, V16, brow, hoff, 0,  sb, 0, tid); CP_COMMIT();
    attn_issue_kv(K16, V16, brow, hoff, 64, sb, 1, tid); CP_COMMIT();

    cp_wait<2>();
    __syncthreads();

    uint32_t aq[4][4];
    {
        const int a_lm = (lane & 15) * APAD + (lane >> 4) * 8;
        #pragma unroll
        for (int kk = 0; kk < 4; kk++) {
            uint32_t ad = sb + (uint32_t)(AO_Q + wm * APAD + a_lm + kk * 16) * 2;
            LDMX4(aq[kk][0], aq[kk][1], aq[kk][2], aq[kk][3], ad);
        }
    }

    float o[8][4] = {};
    float l0r = 0.f, l1r = 0.f;
    const int mrow0 = q0 + wm + g;
    const int NKT = SS / 64;

    const int k_lm = ((lane >> 4) * 8 + (lane & 7)) * APAD + ((lane >> 3) & 1) * 8;
    const int v_lm = (lane & 15) * APAD + (lane >> 4) * 8;
    const uint32_t* pr0 = pm + (brow + mrow0) * (SS / 32);
    const uint32_t* pr1 = pr0 + 8 * (SS / 32);
    const int s0 = 2 * t;

    for (int it = 0; it < NKT; it++) {
        // Hoist mask words: gmem latency hides under the S MMAs below
        uint2 w0 = *(const uint2*)(pr0 + it * 2);
        uint2 w1 = *(const uint2*)(pr1 + it * 2);

        cp_wait<1>();
        __syncthreads();

        const int buf = it & 1;
        const uint32_t kbase = sb + (uint32_t)AO_K(buf) * 2;
        const uint32_t vbase = sb + (uint32_t)(AO_V(buf) + v_lm) * 2;

        // ---- S = Q @ K^T (fp16 1-pass) ----
        float cs[8][4] = {};
        #pragma unroll
        for (int kk = 0; kk < 4; kk++) {
            const int k0 = kk * 16;
            #pragma unroll
            for (int j = 0; j < 4; j++) {
                uint32_t kd = kbase + (uint32_t)(2 * j * 8 * APAD + k_lm + k0) * 2;
                uint32_t bh[4];
                LDMX4(bh[0], bh[1], bh[2], bh[3], kd);
                mma_f16(cs[2 * j],     aq[kk], &bh[0]);
                mma_f16(cs[2 * j + 1], aq[kk], &bh[2]);
            }
        }

        // ---- P = ex2(S) (q pre-scaled), masked -> 0; accumulate row sums ----
        #pragma unroll
        for (int nt = 0; nt < 8; nt++) {
            const uint32_t wa = (nt < 4) ? w0.x : w0.y;
            const uint32_t wb = (nt < 4) ? w1.x : w1.y;
            const int p = 8 * (nt & 3) + s0;
            float e0 = ex2(cs[nt][0]);
            float e1 = ex2(cs[nt][1]);
            float e2 = ex2(cs[nt][2]);
            float e3 = ex2(cs[nt][3]);
            cs[nt][0] = ((wa >> p) & 1)       ? 0.f : e0;
            cs[nt][1] = ((wa >> (p + 1)) & 1) ? 0.f : e1;
            cs[nt][2] = ((wb >> p) & 1)       ? 0.f : e2;
            cs[nt][3] = ((wb >> (p + 1)) & 1) ? 0.f : e3;
            l0r += cs[nt][0] + cs[nt][1];
            l1r += cs[nt][2] + cs[nt][3];
        }

        // ---- O += P @ V (fp16 1-pass), V via ldmatrix.x4.trans ----
        #pragma unroll
        for (int kk = 0; kk < 4; kk++) {
            uint32_t ap[4];
            ap[0] = pack_f16(__float2half_rn(cs[2*kk][0]),   __float2half_rn(cs[2*kk][1]));
            ap[1] = pack_f16(__float2half_rn(cs[2*kk][2]),   __float2half_rn(cs[2*kk][3]));
            ap[2] = pack_f16(__float2half_rn(cs[2*kk+1][0]), __float2half_rn(cs[2*kk+1][1]));
            ap[3] = pack_f16(__float2half_rn(cs[2*kk+1][2]), __float2half_rn(cs[2*kk+1][3]));
            const uint32_t koff = kk * 16 * APAD * 2;
            #pragma unroll
            for (int np = 0; np < 4; np++) {
                uint32_t bh[4];
                LDMX4T(bh[0], bh[1], bh[2], bh[3], vbase + koff + np * 32);
                mma_f16(o[2 * np],     ap, &bh[0]);
                mma_f16(o[2 * np + 1], ap, &bh[2]);
            }
        }

        __syncthreads();
        if (it + 2 < NKT) {
            attn_issue_kv(K16, V16, brow, hoff, (it + 2) * 64, sb, buf, tid);
            CP_COMMIT();
        }
    }

    // ---- single row-sum reduction over t-lanes ----
    l0r += __shfl_xor_sync(0xFFFFFFFF, l0r, 1);
    l0r += __shfl_xor_sync(0xFFFFFFFF, l0r, 2);
    l1r += __shfl_xor_sync(0xFFFFFFFF, l1r, 1);
    l1r += __shfl_xor_sync(0xFFFFFFFF, l1r, 2);

    float inv0 = 1.f / l0r, inv1 = 1.f / l1r;
    const size_t r0 = brow + q0 + wm + g;
    #pragma unroll
    for (int nt = 0; nt < 8; nt++) {
        const int n = nt * 8 + 2 * t;
        uint32_t u0 = pack_f16(__float2half_rn(o[nt][0] * inv0),
                               __float2half_rn(o[nt][1] * inv0));
        uint32_t u1 = pack_f16(__float2half_rn(o[nt][2] * inv1),
                               __float2half_rn(o[nt][3] * inv1));
        *(uint32_t*)&O16[r0 * DD + hoff + n] = u0;
        *(uint32_t*)&O16[(r0 + 8) * DD + hoff + n] = u1;
    }
}

// ---------------------------------------------------------------------------
extern "C" void kernel_launch(void* const* d_in, const int* in_sizes, int n_in,
                              void* d_out, int out_size)
{
    const float* x    = (const float*)d_in[0];
    const int*   mask = (const int*)  d_in[1];
    const float* Wq   = (const float*)d_in[2];
    const float* Wk   = (const float*)d_in[3];
    const float* Wv   = (const float*)d_in[4];
    const float* Wo   = (const float*)d_in[5];
    const float* bo   = (const float*)d_in[6];
    float* out = (float*)d_out;

    f16 *x16, *wq16, *wk16, *wv16, *wo16;
    f16 *q16, *k16, *v16, *a16;
    uint32_t* pmp;
    cudaGetSymbolAddress((void**)&x16, g_x16);
    cudaGetSymbolAddress((void**)&wq16, g_wq16); cudaGetSymbolAddress((void**)&wk16, g_wk16);
    cudaGetSymbolAddress((void**)&wv16, g_wv16); cudaGetSymbolAddress((void**)&wo16, g_wo16);
    cudaGetSymbolAddress((void**)&q16, g_q16);   cudaGetSymbolAddress((void**)&k16, g_k16);
    cudaGetSymbolAddress((void**)&v16, g_v16);   cudaGetSymbolAddress((void**)&a16, g_a16);
    cudaGetSymbolAddress((void**)&pmp, g_pm);

    cudaFuncSetAttribute(qkv_gemm, cudaFuncAttributeMaxDynamicSharedMemorySize, GEMM1_SMEM);
    cudaFuncSetAttribute(out_gemm, cudaFuncAttributeMaxDynamicSharedMemorySize, GEMM1_SMEM);
    cudaFuncSetAttribute(attn_kernel, cudaFuncAttributeMaxDynamicSharedMemorySize, ATTN_SMEM);

    prep_all<<<(NPREP + 255) / 256, 256>>>(x, Wq, Wk, Wv, Wo, mask,
                                           x16, wq16, wk16, wv16, wo16, pmp);

    dim3 gq(DD / 128, MM / 128, 3);
    qkv_gemm<<<gq, 256, GEMM1_SMEM>>>(x16, wq16, wk16, wv16, q16, k16, v16);

    attn_kernel<<<dim3(SS / 64, HH, BB), 128, ATTN_SMEM>>>(
        q16, k16, v16, pmp, a16);

    dim3 go(DD / 128, MM / 128);
    out_gemm<<<go, 256, GEMM1_SMEM>>>(a16, wo16, bo, out);
}

// round 16
// speedup vs baseline: 1.7332x; 1.0604x over previous
#include <cuda_runtime.h>
#include <cuda_fp16.h>
#include <math.h>
#include <stdint.h>

#define BB 2
#define SS 2048
#define DD 1024
#define HH 16
#define HDIM 64
#define MM (BB*SS)

typedef __half f16;

// ---------------------------------------------------------------------------
// Scratch (__device__ globals; no runtime allocation)
// ---------------------------------------------------------------------------
__device__ f16 g_x16[MM*DD];
__device__ f16 g_wq16[DD*DD], g_wk16[DD*DD], g_wv16[DD*DD], g_wo16[DD*DD];
__device__ f16 g_q16[MM*DD], g_k16[MM*DD], g_v16[MM*DD], g_a16[MM*DD];
#define NMW (BB * SS * (SS / 32))
__device__ uint32_t g_pm[NMW];

// ---------------------------------------------------------------------------
// Helpers
// ---------------------------------------------------------------------------
__device__ __forceinline__ uint32_t pack_f16(f16 a, f16 b) {
    __half2 t = __halves2half2(a, b);
    return *reinterpret_cast<uint32_t*>(&t);
}

__device__ __forceinline__ float ex2(float x) {
    float r;
    asm("ex2.approx.ftz.f32 %0, %1;" : "=f"(r) : "f"(x));
    return r;
}

__device__ __forceinline__ void mma_f16(float* c, const uint32_t* a, const uint32_t* b) {
    asm volatile(
        "mma.sync.aligned.m16n8k16.row.col.f32.f16.f16.f32 "
        "{%0,%1,%2,%3}, {%4,%5,%6,%7}, {%8,%9}, {%0,%1,%2,%3};\n"
        : "+f"(c[0]), "+f"(c[1]), "+f"(c[2]), "+f"(c[3])
        : "r"(a[0]), "r"(a[1]), "r"(a[2]), "r"(a[3]), "r"(b[0]), "r"(b[1]));
}

__device__ __forceinline__ uint32_t smem_u32(const void* p) {
    return (uint32_t)__cvta_generic_to_shared(p);
}

#define CP16(sa, gp) \
    asm volatile("cp.async.cg.shared.global [%0], [%1], 16;\n" :: "r"(sa), "l"(gp))
#define CP_COMMIT() asm volatile("cp.async.commit_group;\n" ::: "memory")
template<int N>
__device__ __forceinline__ void cp_wait() {
    asm volatile("cp.async.wait_group %0;\n" :: "n"(N) : "memory");
}

#define LDMX4T(r0, r1, r2, r3, addr) \
    asm volatile("ldmatrix.sync.aligned.m8n8.x4.trans.shared.b16 {%0,%1,%2,%3}, [%4];\n" \
                 : "=r"(r0), "=r"(r1), "=r"(r2), "=r"(r3) : "r"(addr))
#define LDMX4(r0, r1, r2, r3, addr) \
    asm volatile("ldmatrix.sync.aligned.m8n8.x4.shared.b16 {%0,%1,%2,%3}, [%4];\n" \
                 : "=r"(r0), "=r"(r1), "=r"(r2), "=r"(r3) : "r"(addr))

// softmax in exp2 domain: 0.125 * log2(e), folded into q at qkv epilogue
#define SCL2 0.18033688011112042f

// ---------------------------------------------------------------------------
// Fused prep kernel: fp32->fp16 conversions + 1-bit mask pack
// ---------------------------------------------------------------------------
#define NX4 (MM * DD / 4)
#define NW4 (DD * DD / 4)
#define NSPLIT (NX4 + 4 * NW4)
#define NPREP (NSPLIT + NMW)

__global__ void prep_all(const float* __restrict__ x,
                         const float* __restrict__ wq, const float* __restrict__ wk,
                         const float* __restrict__ wv, const float* __restrict__ wo,
                         const int* __restrict__ mask,
                         f16* __restrict__ x16,
                         f16* __restrict__ wq16, f16* __restrict__ wk16,
                         f16* __restrict__ wv16, f16* __restrict__ wo16,
                         uint32_t* __restrict__ pm) {
    int i = blockIdx.x * blockDim.x + threadIdx.x;
    if (i >= NPREP) return;
    if (i < NSPLIT) {
        const float* s; f16* d; int off;
        if (i < NX4)                { s = x;  d = x16;  off = i; }
        else if (i < NX4 + NW4)     { s = wq; d = wq16; off = i - NX4; }
        else if (i < NX4 + 2 * NW4) { s = wk; d = wk16; off = i - NX4 - NW4; }
        else if (i < NX4 + 3 * NW4) { s = wv; d = wv16; off = i - NX4 - 2 * NW4; }
        else                        { s = wo; d = wo16; off = i - NX4 - 3 * NW4; }
        float4 v = ((const float4*)s)[off];
        uint2 u;
        u.x = pack_f16(__float2half_rn(v.x), __float2half_rn(v.y));
        u.y = pack_f16(__float2half_rn(v.z), __float2half_rn(v.w));
        ((uint2*)d)[off] = u;
    } else {
        int w = i - NSPLIT;
        const int4* src = (const int4*)(mask + (size_t)w * 32);
        uint32_t bits = 0;
        #pragma unroll
        for (int j = 0; j < 8; j++) {
            int4 m = src[j];
            bits |= (uint32_t)(m.x == 1) << (4 * j);
            bits |= (uint32_t)(m.y == 1) << (4 * j + 1);
            bits |= (uint32_t)(m.z == 1) << (4 * j + 2);
            bits |= (uint32_t)(m.w == 1) << (4 * j + 3);
        }
        pm[w] = bits;
    }
}

// ---------------------------------------------------------------------------
// fp16 single-pass GEMM: 128x128 CTA tile, 8 warps, 4-stage cp.async ring,
// ONE sync per chunk (write buffer = read buffer of ch-1, protected by sync).
// ---------------------------------------------------------------------------
#define GKC 32
#define GPAD 40
#define GA_ELE (128 * GPAD)
#define GB_ELE (128 * GPAD)
#define G1STG (GA_ELE + GB_ELE)
#define G1O_WH GA_ELE
#define GNS 4
#define GEMM1_SMEM (GNS * G1STG * 2)   // 81920 bytes

__device__ __forceinline__ void gemm1_issue(const f16* __restrict__ A,
                                            const f16* __restrict__ W,
                                            int m0, int n0, int kt,
                                            uint32_t sbase, int tid) {
    #pragma unroll
    for (int j = 0; j < 2; j++) {
        int cidx = tid + 256 * j;
        int row = cidx >> 2, col = (cidx & 3) * 8;
        uint32_t so = sbase + (row * GPAD + col) * 2;
        CP16(so, A + (size_t)(m0 + row) * DD + kt + col);
    }
    #pragma unroll
    for (int j = 0; j < 2; j++) {
        int cidx = tid + 256 * j;
        int row = cidx >> 2, col = (cidx & 3) * 8;
        uint32_t so = sbase + (G1O_WH + row * GPAD + col) * 2;
        CP16(so, W + (size_t)(n0 + row) * DD + kt + col);
    }
}

__device__ __forceinline__ void gemm1_main(const f16* __restrict__ A,
                                           const f16* __restrict__ W,
                                           int m0, int n0,
                                           float c[2][8][4]) {
    extern __shared__ f16 sm16[];
    const uint32_t sb = smem_u32(sm16);
    const int tid = threadIdx.x;
    const int wid = tid >> 5, lane = tid & 31;
    const int wm = (wid >> 1) * 32, wn = (wid & 1) * 64;
    const int a_lm = (lane & 15) * GPAD + (lane >> 4) * 8;
    const int b_lm = (wn + (lane >> 4) * 8 + (lane & 7)) * GPAD + ((lane >> 3) & 1) * 8;

    gemm1_issue(A, W, m0, n0, 0,       sb,                 tid); CP_COMMIT();
    gemm1_issue(A, W, m0, n0, GKC,     sb + G1STG * 2,     tid); CP_COMMIT();
    gemm1_issue(A, W, m0, n0, 2 * GKC, sb + 2 * G1STG * 2, tid); CP_COMMIT();

    const int NCH = DD / GKC;
    for (int ch = 0; ch < NCH; ch++) {
        cp_wait<2>();          // chunk ch resident
        __syncthreads();       // all warps done reading chunk ch-1's buffer
        if (ch + 3 < NCH) {    // write into (ch+3)%4 == (ch-1)%4 — safe
            gemm1_issue(A, W, m0, n0, (ch + 3) * GKC,
                        sb + ((ch + 3) % GNS) * G1STG * 2, tid);
            CP_COMMIT();
        }

        const uint32_t sA = sb + ((ch % GNS) * G1STG) * 2;

        #pragma unroll
        for (int ks = 0; ks < 2; ks++) {
            const int k0 = ks * 16;
            uint32_t ah[2][4];
            #pragma unroll
            for (int mt = 0; mt < 2; mt++) {
                uint32_t ad = sA + (uint32_t)((wm + mt * 16) * GPAD + a_lm + k0) * 2;
                LDMX4(ah[mt][0], ah[mt][1], ah[mt][2], ah[mt][3], ad);
            }
            #pragma unroll
            for (int j = 0; j < 4; j++) {
                uint32_t bd = sA + (uint32_t)(G1O_WH + 2 * j * 8 * GPAD + b_lm + k0) * 2;
                uint32_t bh[4];
                LDMX4(bh[0], bh[1], bh[2], bh[3], bd);
                #pragma unroll
                for (int sub = 0; sub < 2; sub++) {
                    const int nt = 2 * j + sub;
                    #pragma unroll
                    for (int mt = 0; mt < 2; mt++)
                        mma_f16(c[mt][nt], ah[mt], &bh[2 * sub]);
                }
            }
        }
    }
}

__global__ void __launch_bounds__(256, 2)
qkv_gemm(const f16* __restrict__ x16,
         const f16* __restrict__ wq16, const f16* __restrict__ wk16,
         const f16* __restrict__ wv16,
         f16* __restrict__ q16, f16* __restrict__ k16, f16* __restrict__ v16) {
    const int z = blockIdx.z;
    const f16* Wh = (z == 0) ? wq16 : (z == 1) ? wk16 : wv16;
    f16* Y = (z == 0) ? q16 : (z == 1) ? k16 : v16;
    const int m0 = blockIdx.y * 128, n0 = blockIdx.x * 128;
    const int tid = threadIdx.x;
    const int wid = tid >> 5, lane = tid & 31;
    const int g = lane >> 2, t = lane & 3;
    const int wm = (wid >> 1) * 32, wn = (wid & 1) * 64;

    float c[2][8][4] = {};
    gemm1_main(x16, Wh, m0, n0, c);

    const float qs = (z == 0) ? SCL2 : 1.0f;

    #pragma unroll
    for (int mt = 0; mt < 2; mt++) {
        const int r = m0 + wm + mt * 16 + g;
        #pragma unroll
        for (int nt = 0; nt < 8; nt++) {
            const int n = n0 + wn + nt * 8 + 2 * t;
            uint32_t u0 = pack_f16(__float2half_rn(c[mt][nt][0] * qs),
                                   __float2half_rn(c[mt][nt][1] * qs));
            uint32_t u1 = pack_f16(__float2half_rn(c[mt][nt][2] * qs),
                                   __float2half_rn(c[mt][nt][3] * qs));
            *(uint32_t*)&Y[(size_t)r * DD + n] = u0;
            *(uint32_t*)&Y[(size_t)(r + 8) * DD + n] = u1;
        }
    }
}

__global__ void __launch_bounds__(256, 2)
out_gemm(const f16* __restrict__ a16, const f16* __restrict__ wo16,
         const float* __restrict__ bo, float* __restrict__ out) {
    const int m0 = blockIdx.y * 128, n0 = blockIdx.x * 128;
    const int tid = threadIdx.x;
    const int wid = tid >> 5, lane = tid & 31;
    const int g = lane >> 2, t = lane & 3;
    const int wm = (wid >> 1) * 32, wn = (wid & 1) * 64;

    float c[2][8][4] = {};
    gemm1_main(a16, wo16, m0, n0, c);

    #pragma unroll
    for (int mt = 0; mt < 2; mt++) {
        const int r = m0 + wm + mt * 16 + g;
        #pragma unroll
        for (int nt = 0; nt < 8; nt++) {
            const int n = n0 + wn + nt * 8 + 2 * t;
            float bx = bo[n], by = bo[n + 1];
            float2 o0 = { c[mt][nt][0] + bx, c[mt][nt][1] + by };
            float2 o1 = { c[mt][nt][2] + bx, c[mt][nt][3] + by };
            *(float2*)&out[(size_t)r * DD + n] = o0;
            *(float2*)&out[(size_t)(r + 8) * DD + n] = o1;
        }
    }
}

// ---------------------------------------------------------------------------
// Flash attention: 64 q-rows/CTA, 4 warps x 16 rows, fp16 1-pass MMAs,
// no-max MUFU.EX2 softmax (q pre-scaled), 3-buffer KV ring with ONE sync/iter,
// packed mask (hoisted), V via ldmatrix.x4.trans. 128 thr, 3 CTAs/SM.
// ---------------------------------------------------------------------------
#define APAD 72
#define AT_ELE (64 * APAD)
#define AO_Q 0
#define AO_K(s) ((1 + 2 * (s)) * AT_ELE)
#define AO_V(s) ((2 + 2 * (s)) * AT_ELE)
#define ATTN_SMEM (7 * AT_ELE * 2)   // Q + 3x(K+V) = 64512 bytes

__device__ __forceinline__ void attn_issue_kv(const f16* __restrict__ K16,
                                              const f16* __restrict__ V16,
                                              size_t brow, size_t hoff, int kt,
                                              uint32_t sb, int s, int tid) {
    #pragma unroll
    for (int j = 0; j < 4; j++) {
        int cidx = tid + 128 * j;
        int row = cidx >> 3, col = (cidx & 7) * 8;
        uint32_t so = sb + (AO_K(s) + row * APAD + col) * 2;
        size_t go = (brow + kt + row) * DD + hoff + col;
        CP16(so,              K16 + go);
        CP16(so + AT_ELE * 2, V16 + go);
    }
}

__global__ void __launch_bounds__(128, 3)
attn_kernel(const f16* __restrict__ Q16,
            const f16* __restrict__ K16, const f16* __restrict__ V16,
            const uint32_t* __restrict__ pm,
            f16* __restrict__ O16)
{
    extern __shared__ f16 smA[];
    const uint32_t sb = smem_u32(smA);
    const int tid = threadIdx.x;
    const int wid = tid >> 5, lane = tid & 31;
    const int g = lane >> 2, t = lane & 3;
    const int q0 = blockIdx.x * 64;
    const int h = blockIdx.y;
    const int b = blockIdx.z;
    const int wm = wid * 16;

    const size_t hoff = (size_t)h * HDIM;
    const size_t brow = (size_t)b * SS;

    #pragma unroll
    for (int j = 0; j < 4; j++) {
        int cidx = tid + 128 * j;
        int row = cidx >> 3, col = (cidx & 7) * 8;
        uint32_t so = sb + (AO_Q + row * APAD + col) * 2;
        CP16(so, Q16 + (brow + q0 + row) * DD + hoff + col);
    }
    CP_COMMIT();
    attn_issue_kv(K16, V16, brow, hoff, 0,  sb, 0, tid); CP_COMMIT();
    attn_issue_kv(K16, V16, brow, hoff, 64, sb, 1, tid); CP_COMMIT();

    cp_wait<2>();    // Q resident
    __syncthreads();

    uint32_t aq[4][4];
    {
        const int a_lm = (lane & 15) * APAD + (lane >> 4) * 8;
        #pragma unroll
        for (int kk = 0; kk < 4; kk++) {
            uint32_t ad = sb + (uint32_t)(AO_Q + wm * APAD + a_lm + kk * 16) * 2;
            LDMX4(aq[kk][0], aq[kk][1], aq[kk][2], aq[kk][3], ad);
        }
    }

    float o[8][4] = {};
    float l0r = 0.f, l1r = 0.f;
    const int mrow0 = q0 + wm + g;
    const int NKT = SS / 64;

    const int k_lm = ((lane >> 4) * 8 + (lane & 7)) * APAD + ((lane >> 3) & 1) * 8;
    const int v_lm = (lane & 15) * APAD + (lane >> 4) * 8;
    const uint32_t* pr0 = pm + (brow + mrow0) * (SS / 32);
    const uint32_t* pr1 = pr0 + 8 * (SS / 32);
    const int s0 = 2 * t;

    for (int it = 0; it < NKT; it++) {
        // Hoist mask words (latency hides under MMAs)
        uint2 w0 = *(const uint2*)(pr0 + it * 2);
        uint2 w1 = *(const uint2*)(pr1 + it * 2);

        cp_wait<1>();      // KV(it) resident, KV(it+1) may be in flight
        __syncthreads();   // all warps done reading KV(it-1)'s buffer
        if (it + 2 < NKT) {  // write (it+2)%3 == (it-1)%3 — safe
            attn_issue_kv(K16, V16, brow, hoff, (it + 2) * 64,
                          sb, (it + 2) % 3, tid);
            CP_COMMIT();
        }

        const int buf = it % 3;
        const uint32_t kbase = sb + (uint32_t)AO_K(buf) * 2;
        const uint32_t vbase = sb + (uint32_t)(AO_V(buf) + v_lm) * 2;

        // ---- S = Q @ K^T (fp16 1-pass) ----
        float cs[8][4] = {};
        #pragma unroll
        for (int kk = 0; kk < 4; kk++) {
            const int k0 = kk * 16;
            #pragma unroll
            for (int j = 0; j < 4; j++) {
                uint32_t kd = kbase + (uint32_t)(2 * j * 8 * APAD + k_lm + k0) * 2;
                uint32_t bh[4];
                LDMX4(bh[0], bh[1], bh[2], bh[3], kd);
                mma_f16(cs[2 * j],     aq[kk], &bh[0]);
                mma_f16(cs[2 * j + 1], aq[kk], &bh[2]);
            }
        }

        // ---- P = ex2(S), masked -> 0; accumulate row sums ----
        #pragma unroll
        for (int nt = 0; nt < 8; nt++) {
            const uint32_t wa = (nt < 4) ? w0.x : w0.y;
            const uint32_t wb = (nt < 4) ? w1.x : w1.y;
            const int p = 8 * (nt & 3) + s0;
            float e0 = ex2(cs[nt][0]);
            float e1 = ex2(cs[nt][1]);
            float e2 = ex2(cs[nt][2]);
            float e3 = ex2(cs[nt][3]);
            cs[nt][0] = ((wa >> p) & 1)       ? 0.f : e0;
            cs[nt][1] = ((wa >> (p + 1)) & 1) ? 0.f : e1;
            cs[nt][2] = ((wb >> p) & 1)       ? 0.f : e2;
            cs[nt][3] = ((wb >> (p + 1)) & 1) ? 0.f : e3;
            l0r += cs[nt][0] + cs[nt][1];
            l1r += cs[nt][2] + cs[nt][3];
        }

        // ---- O += P @ V (fp16 1-pass), V via ldmatrix.x4.trans ----
        #pragma unroll
        for (int kk = 0; kk < 4; kk++) {
            uint32_t ap[4];
            ap[0] = pack_f16(__float2half_rn(cs[2*kk][0]),   __float2half_rn(cs[2*kk][1]));
            ap[1] = pack_f16(__float2half_rn(cs[2*kk][2]),   __float2half_rn(cs[2*kk][3]));
            ap[2] = pack_f16(__float2half_rn(cs[2*kk+1][0]), __float2half_rn(cs[2*kk+1][1]));
            ap[3] = pack_f16(__float2half_rn(cs[2*kk+1][2]), __float2half_rn(cs[2*kk+1][3]));
            const uint32_t koff = kk * 16 * APAD * 2;
            #pragma unroll
            for (int np = 0; np < 4; np++) {
                uint32_t bh[4];
                LDMX4T(bh[0], bh[1], bh[2], bh[3], vbase + koff + np * 32);
                mma_f16(o[2 * np],     ap, &bh[0]);
                mma_f16(o[2 * np + 1], ap, &bh[2]);
            }
        }
    }

    // ---- single row-sum reduction over t-lanes ----
    l0r += __shfl_xor_sync(0xFFFFFFFF, l0r, 1);
    l0r += __shfl_xor_sync(0xFFFFFFFF, l0r, 2);
    l1r += __shfl_xor_sync(0xFFFFFFFF, l1r, 1);
    l1r += __shfl_xor_sync(0xFFFFFFFF, l1r, 2);

    float inv0 = 1.f / l0r, inv1 = 1.f / l1r;
    const size_t r0 = brow + q0 + wm + g;
    #pragma unroll
    for (int nt = 0; nt < 8; nt++) {
        const int n = nt * 8 + 2 * t;
        uint32_t u0 = pack_f16(__float2half_rn(o[nt][0] * inv0),
                               __float2half_rn(o[nt][1] * inv0));
        uint32_t u1 = pack_f16(__float2half_rn(o[nt][2] * inv1),
                               __float2half_rn(o[nt][3] * inv1));
        *(uint32_t*)&O16[r0 * DD + hoff + n] = u0;
        *(uint32_t*)&O16[(r0 + 8) * DD + hoff + n] = u1;
    }
}

// ---------------------------------------------------------------------------
extern "C" void kernel_launch(void* const* d_in, const int* in_sizes, int n_in,
                              void* d_out, int out_size)
{
    const float* x    = (const float*)d_in[0];
    const int*   mask = (const int*)  d_in[1];
    const float* Wq   = (const float*)d_in[2];
    const float* Wk   = (const float*)d_in[3];
    const float* Wv   = (const float*)d_in[4];
    const float* Wo   = (const float*)d_in[5];
    const float* bo   = (const float*)d_in[6];
    float* out = (float*)d_out;

    f16 *x16, *wq16, *wk16, *wv16, *wo16;
    f16 *q16, *k16, *v16, *a16;
    uint32_t* pmp;
    cudaGetSymbolAddress((void**)&x16, g_x16);
    cudaGetSymbolAddress((void**)&wq16, g_wq16); cudaGetSymbolAddress((void**)&wk16, g_wk16);
    cudaGetSymbolAddress((void**)&wv16, g_wv16); cudaGetSymbolAddress((void**)&wo16, g_wo16);
    cudaGetSymbolAddress((void**)&q16, g_q16);   cudaGetSymbolAddress((void**)&k16, g_k16);
    cudaGetSymbolAddress((void**)&v16, g_v16);   cudaGetSymbolAddress((void**)&a16, g_a16);
    cudaGetSymbolAddress((void**)&pmp, g_pm);

    cudaFuncSetAttribute(qkv_gemm, cudaFuncAttributeMaxDynamicSharedMemorySize, GEMM1_SMEM);
    cudaFuncSetAttribute(out_gemm, cudaFuncAttributeMaxDynamicSharedMemorySize, GEMM1_SMEM);
    cudaFuncSetAttribute(attn_kernel, cudaFuncAttributeMaxDynamicSharedMemorySize, ATTN_SMEM);

    prep_all<<<(NPREP + 255) / 256, 256>>>(x, Wq, Wk, Wv, Wo, mask,
                                           x16, wq16, wk16, wv16, wo16, pmp);

    dim3 gq(DD / 128, MM / 128, 3);
    qkv_gemm<<<gq, 256, GEMM1_SMEM>>>(x16, wq16, wk16, wv16, q16, k16, v16);

    attn_kernel<<<dim3(SS / 64, HH, BB), 128, ATTN_SMEM>>>(
        q16, k16, v16, pmp, a16);

    dim3 go(DD / 128, MM / 128);
    out_gemm<<<go, 256, GEMM1_SMEM>>>(a16, wo16, bo, out);
}